// round 14
// baseline (speedup 1.0000x reference)
#include <cuda_runtime.h>

#define NPTS     100000
#define BATCH    4096
#define KSEL     10
#define TPB      256
#define RPB      8
#define GRID     (BATCH / RPB)     // 512 blocks
#define SAMPLE   8192              // threshold sample size
#define CAP      704               // candidate capacity per ray (mean ~122)
#define MITERS   195               // 195*256 = 49920 per half
#define HALF     49920
#define TAILBASE 99840             // tail: 160 points

__device__ float4 g_packed[NPTS];  // (x, y, z, |x|^2)

__global__ __launch_bounds__(256)
void pack_kernel(const float* __restrict__ xyz)
{
    int i = blockIdx.x * 256 + threadIdx.x;
    if (i < NPTS) {
        float x = xyz[i * 3 + 0];
        float y = xyz[i * 3 + 1];
        float z = xyz[i * 3 + 2];
        float q = fmaf(x, x, fmaf(y, y, z * z));
        g_packed[i] = make_float4(x, y, z, q);
    }
}

__global__ __launch_bounds__(TPB)
void gs_kernel(const float* __restrict__ rays_o,
               const float* __restrict__ rays_d,
               const float* __restrict__ fdc,
               const float* __restrict__ opac,
               float* __restrict__ out)
{
    __shared__ float scx[RPB], scy[RPB], scz[RPB], sC[RPB];
    __shared__ float sT[RPB];              // threshold (s-domain)
    __shared__ int   cnt[RPB];
    __shared__ float cd2 [RPB * CAP];      // phase1 merge lists / candidates / phase3 lists
    __shared__ int   cidx[RPB * CAP];
    volatile float* sTv = sT;

    const int t    = threadIdx.x;
    const int lane = t & 31;
    const int w    = t >> 5;               // warp 0..7
    const int rayBase = blockIdx.x * RPB;

    if (t < RPB) {
        int r = rayBase + t;
        float cx = fmaf(3.0f, rays_d[r*3+0], rays_o[r*3+0]);
        float cy = fmaf(3.0f, rays_d[r*3+1], rays_o[r*3+1]);
        float cz = fmaf(3.0f, rays_d[r*3+2], rays_o[r*3+2]);
        scx[t] = -2.0f * cx;               // s = q + cx'*x + cy'*y + cz'*z
        scy[t] = -2.0f * cy;
        scz[t] = -2.0f * cz;
        sC[t]  = cx*cx + cy*cy + cz*cz;    // d^2 = s + C
        sT[t]  = 3.0e38f;
        cnt[t] = 0;
    }
    __syncthreads();

    // ---------- Phase 1: exact top-10 over SAMPLE points -> threshold ----------
    {
        const int rl  = t & 7;             // ray
        const int sub = t >> 3;            // 0..31
        const float cxp = scx[rl], cyp = scy[rl], czp = scz[rl];
        float best[KSEL];
#pragma unroll
        for (int j = 0; j < KSEL; j++) best[j] = 3.0e38f;
        float tloc = 3.0e38f;

#pragma unroll 4
        for (int c = 0; c < SAMPLE / 32; c++) {
            float4 p = g_packed[sub + c * 32];
            float s = fmaf(cxp, p.x, fmaf(cyp, p.y, fmaf(czp, p.z, p.w)));
            if (s < fminf(sTv[rl], tloc)) {
                float v = s;
#pragma unroll
                for (int j = 0; j < KSEL; j++) {
                    if (v < best[j]) { float tv = best[j]; best[j] = v; v = tv; }
                }
                tloc = best[KSEL-1];
                if (tloc < sTv[rl]) sTv[rl] = tloc;   // benign race: any value is a valid bound
            }
        }
        float* smrg = cd2;                 // values-only merge lists
#pragma unroll
        for (int j = 0; j < KSEL; j++) smrg[(rl*32 + sub)*KSEL + j] = best[j];
        __syncthreads();

        for (int stride = 16; stride >= 1; stride >>= 1) {
            if (sub < stride) {
                int a = (rl*32 + sub)*KSEL, b = (rl*32 + sub + stride)*KSEL;
                float ov[KSEL]; int ia = 0, ib = 0;
#pragma unroll
                for (int k = 0; k < KSEL; k++) {
                    float va = smrg[a + ia], vb = smrg[b + ib];
                    if (va <= vb) { ov[k] = va; ia++; } else { ov[k] = vb; ib++; }
                }
#pragma unroll
                for (int k = 0; k < KSEL; k++) smrg[a + k] = ov[k];
            }
            __syncthreads();
        }
        if (t < RPB) { sT[t] = cd2[(t*32)*KSEL + KSEL-1]; cnt[t] = 0; }
        __syncthreads();
    }

    // ---------- Phase 2: lane-owned filter scan (1 LDG.128 per point) ----------
    {
        const float c0x = scx[0], c0y = scy[0], c0z = scz[0], T0 = sT[0], C0 = sC[0];
        const float c1x = scx[1], c1y = scy[1], c1z = scz[1], T1 = sT[1], C1 = sC[1];
        const float c2x = scx[2], c2y = scy[2], c2z = scz[2], T2 = sT[2], C2 = sC[2];
        const float c3x = scx[3], c3y = scy[3], c3z = scz[3], T3 = sT[3], C3 = sC[3];
        const float c4x = scx[4], c4y = scy[4], c4z = scz[4], T4 = sT[4], C4 = sC[4];
        const float c5x = scx[5], c5y = scy[5], c5z = scz[5], T5 = sT[5], C5 = sC[5];
        const float c6x = scx[6], c6y = scy[6], c6z = scz[6], T6 = sT[6], C6 = sC[6];
        const float c7x = scx[7], c7y = scy[7], c7z = scz[7], T7 = sT[7], C7 = sC[7];

#define PUSH(SV, TR, CR, KK, R) \
        if ((SV) <= (TR)) { int _p = atomicAdd(&cnt[R], 1); \
            if (_p < CAP) { cd2[(R)*CAP + _p] = (SV) + (CR); cidx[(R)*CAP + _p] = (KK); } }

        const int stripe = w * 32 + lane;
        const float4* pA = g_packed + stripe;
        const float4* pB = g_packed + stripe + HALF;
#pragma unroll 1
        for (int it = 0; it < MITERS; it++) {
            float4 a = pA[it * 256];
            float4 b = pB[it * 256];

            float sA0 = fmaf(c0x,a.x,fmaf(c0y,a.y,fmaf(c0z,a.z,a.w)));
            float sA1 = fmaf(c1x,a.x,fmaf(c1y,a.y,fmaf(c1z,a.z,a.w)));
            float sA2 = fmaf(c2x,a.x,fmaf(c2y,a.y,fmaf(c2z,a.z,a.w)));
            float sA3 = fmaf(c3x,a.x,fmaf(c3y,a.y,fmaf(c3z,a.z,a.w)));
            float sA4 = fmaf(c4x,a.x,fmaf(c4y,a.y,fmaf(c4z,a.z,a.w)));
            float sA5 = fmaf(c5x,a.x,fmaf(c5y,a.y,fmaf(c5z,a.z,a.w)));
            float sA6 = fmaf(c6x,a.x,fmaf(c6y,a.y,fmaf(c6z,a.z,a.w)));
            float sA7 = fmaf(c7x,a.x,fmaf(c7y,a.y,fmaf(c7z,a.z,a.w)));
            float sB0 = fmaf(c0x,b.x,fmaf(c0y,b.y,fmaf(c0z,b.z,b.w)));
            float sB1 = fmaf(c1x,b.x,fmaf(c1y,b.y,fmaf(c1z,b.z,b.w)));
            float sB2 = fmaf(c2x,b.x,fmaf(c2y,b.y,fmaf(c2z,b.z,b.w)));
            float sB3 = fmaf(c3x,b.x,fmaf(c3y,b.y,fmaf(c3z,b.z,b.w)));
            float sB4 = fmaf(c4x,b.x,fmaf(c4y,b.y,fmaf(c4z,b.z,b.w)));
            float sB5 = fmaf(c5x,b.x,fmaf(c5y,b.y,fmaf(c5z,b.z,b.w)));
            float sB6 = fmaf(c6x,b.x,fmaf(c6y,b.y,fmaf(c6z,b.z,b.w)));
            float sB7 = fmaf(c7x,b.x,fmaf(c7y,b.y,fmaf(c7z,b.z,b.w)));

            int hA = (sA0<=T0) | (sA1<=T1) | (sA2<=T2) | (sA3<=T3)
                   | (sA4<=T4) | (sA5<=T5) | (sA6<=T6) | (sA7<=T7);
            int hB = (sB0<=T0) | (sB1<=T1) | (sB2<=T2) | (sB3<=T3)
                   | (sB4<=T4) | (sB5<=T5) | (sB6<=T6) | (sB7<=T7);
            if (hA | hB) {
                int kA = stripe + it * 256;
                int kB = kA + HALF;
                if (hA) {
                    PUSH(sA0,T0,C0,kA,0) PUSH(sA1,T1,C1,kA,1)
                    PUSH(sA2,T2,C2,kA,2) PUSH(sA3,T3,C3,kA,3)
                    PUSH(sA4,T4,C4,kA,4) PUSH(sA5,T5,C5,kA,5)
                    PUSH(sA6,T6,C6,kA,6) PUSH(sA7,T7,C7,kA,7)
                }
                if (hB) {
                    PUSH(sB0,T0,C0,kB,0) PUSH(sB1,T1,C1,kB,1)
                    PUSH(sB2,T2,C2,kB,2) PUSH(sB3,T3,C3,kB,3)
                    PUSH(sB4,T4,C4,kB,4) PUSH(sB5,T5,C5,kB,5)
                    PUSH(sB6,T6,C6,kB,6) PUSH(sB7,T7,C7,kB,7)
                }
            }
        }
        // Tail: 160 points, one per thread
        if (t < NPTS - TAILBASE) {
            int k = TAILBASE + t;
            float4 p = g_packed[k];
            float s0 = fmaf(c0x,p.x,fmaf(c0y,p.y,fmaf(c0z,p.z,p.w)));
            float s1 = fmaf(c1x,p.x,fmaf(c1y,p.y,fmaf(c1z,p.z,p.w)));
            float s2 = fmaf(c2x,p.x,fmaf(c2y,p.y,fmaf(c2z,p.z,p.w)));
            float s3 = fmaf(c3x,p.x,fmaf(c3y,p.y,fmaf(c3z,p.z,p.w)));
            float s4 = fmaf(c4x,p.x,fmaf(c4y,p.y,fmaf(c4z,p.z,p.w)));
            float s5 = fmaf(c5x,p.x,fmaf(c5y,p.y,fmaf(c5z,p.z,p.w)));
            float s6 = fmaf(c6x,p.x,fmaf(c6y,p.y,fmaf(c6z,p.z,p.w)));
            float s7 = fmaf(c7x,p.x,fmaf(c7y,p.y,fmaf(c7z,p.z,p.w)));
            PUSH(s0,T0,C0,k,0) PUSH(s1,T1,C1,k,1) PUSH(s2,T2,C2,k,2) PUSH(s3,T3,C3,k,3)
            PUSH(s4,T4,C4,k,4) PUSH(s5,T5,C5,k,5) PUSH(s6,T6,C6,k,6) PUSH(s7,T7,C7,k,7)
        }
#undef PUSH
    }
    __syncthreads();

    // ---------- Phase 3: warp w selects exact top-10 of ray w ----------
    {
        int n = cnt[w]; if (n > CAP) n = CAP;
        float best[KSEL]; int bxi[KSEL];
#pragma unroll
        for (int j = 0; j < KSEL; j++) { best[j] = 3.0e38f; bxi[j] = 0; }
        for (int j2 = lane; j2 < n; j2 += 32) {
            float v = cd2[w*CAP + j2]; int ii = cidx[w*CAP + j2];
            if (v < best[KSEL-1]) {
#pragma unroll
                for (int j = 0; j < KSEL; j++) {
                    if (v < best[j]) {
                        float tv = best[j]; int ti = bxi[j];
                        best[j] = v; bxi[j] = ii; v = tv; ii = ti;
                    }
                }
            }
        }
        __syncwarp();                       // all candidate reads done before overwrite
#pragma unroll
        for (int j = 0; j < KSEL; j++) {
            cd2 [w*CAP + lane*KSEL + j] = best[j];
            cidx[w*CAP + lane*KSEL + j] = bxi[j];
        }
        __syncwarp();
        for (int stride = 16; stride >= 1; stride >>= 1) {
            if (lane < stride) {
                int a = w*CAP + lane*KSEL, b = w*CAP + (lane + stride)*KSEL;
                float ov[KSEL]; int oi[KSEL];
                int ia = 0, ib = 0;
#pragma unroll
                for (int k = 0; k < KSEL; k++) {
                    float va = cd2[a + ia], vb = cd2[b + ib];
                    if (va <= vb) { ov[k] = va; oi[k] = cidx[a + ia]; ia++; }
                    else          { ov[k] = vb; oi[k] = cidx[b + ib]; ib++; }
                }
#pragma unroll
                for (int k = 0; k < KSEL; k++) { cd2[a + k] = ov[k]; cidx[a + k] = oi[k]; }
            }
            __syncwarp();
        }
        if (lane == 0) {
            float wsum = 0.f, r0 = 0.f, g0 = 0.f, b0 = 0.f;
#pragma unroll
            for (int k = 0; k < KSEL; k++) {
                float d2 = cd2[w*CAP + k];
                int   ii = cidx[w*CAP + k];
                float d  = sqrtf(fmaxf(d2, 0.0f));
                float op = 1.0f / (1.0f + expf(-opac[ii]));
                float ww = expf(-0.1f * d) * op;
                wsum += ww;
                float a0 = 1.0f / (1.0f + expf(-fdc[ii*3+0]));
                float a1 = 1.0f / (1.0f + expf(-fdc[ii*3+1]));
                float a2 = 1.0f / (1.0f + expf(-fdc[ii*3+2]));
                r0 = fmaf(ww, a0, r0);
                g0 = fmaf(ww, a1, g0);
                b0 = fmaf(ww, a2, b0);
            }
            float inv = 1.0f / (wsum + 1e-8f);
            int ray = rayBase + w;
            out[ray*3+0] = r0 * inv;
            out[ray*3+1] = g0 * inv;
            out[ray*3+2] = b0 * inv;
        }
    }
}

extern "C" void kernel_launch(void* const* d_in, const int* in_sizes, int n_in,
                              void* d_out, int out_size)
{
    const float* rays_o = (const float*)d_in[0];
    const float* rays_d = (const float*)d_in[1];
    const float* xyz    = (const float*)d_in[2];
    const float* fdc    = (const float*)d_in[3];
    const float* opac   = (const float*)d_in[4];
    float* out = (float*)d_out;

    pack_kernel<<<(NPTS + 255) / 256, 256>>>(xyz);
    gs_kernel<<<GRID, TPB>>>(rays_o, rays_d, fdc, opac, out);
}

// round 15
// speedup vs baseline: 1.3508x; 1.3508x over previous
#include <cuda_runtime.h>

#define NPTS     100000
#define BATCH    4096
#define KSEL     10
#define TPB      256
#define RPB      8
#define GRID     (BATCH / RPB)     // 512 blocks
#define SAMPLE   8192              // threshold sample size
#define CAP      704               // candidate capacity per ray (mean ~122)
#define MITERS   195               // 195*256 = 49920 per half
#define HALF     49920
#define TAILBASE 99840             // tail: 160 points

__device__ float4 g_packed[NPTS];  // (x, y, z, |x|^2)

__global__ __launch_bounds__(256)
void pack_kernel(const float* __restrict__ xyz)
{
    int i = blockIdx.x * 256 + threadIdx.x;
    if (i < NPTS) {
        float x = xyz[i * 3 + 0];
        float y = xyz[i * 3 + 1];
        float z = xyz[i * 3 + 2];
        float q = fmaf(x, x, fmaf(y, y, z * z));
        g_packed[i] = make_float4(x, y, z, q);
    }
}

__global__ __launch_bounds__(TPB, 4)   // pin the 64-reg / 4-block boundary
void gs_kernel(const float* __restrict__ rays_o,
               const float* __restrict__ rays_d,
               const float* __restrict__ fdc,
               const float* __restrict__ opac,
               float* __restrict__ out)
{
    __shared__ float scx[RPB], scy[RPB], scz[RPB], sC[RPB];
    __shared__ float sT[RPB];              // threshold (s-domain)
    __shared__ int   cnt[RPB];
    __shared__ float cd2 [RPB * CAP];      // phase1 merge lists / candidates / phase3 lists
    __shared__ int   cidx[RPB * CAP];
    volatile float* sTv = sT;

    const int t    = threadIdx.x;
    const int lane = t & 31;
    const int w    = t >> 5;               // warp 0..7
    const int rayBase = blockIdx.x * RPB;

    if (t < RPB) {
        int r = rayBase + t;
        float cx = fmaf(3.0f, rays_d[r*3+0], rays_o[r*3+0]);
        float cy = fmaf(3.0f, rays_d[r*3+1], rays_o[r*3+1]);
        float cz = fmaf(3.0f, rays_d[r*3+2], rays_o[r*3+2]);
        scx[t] = -2.0f * cx;               // s = q + cx'*x + cy'*y + cz'*z
        scy[t] = -2.0f * cy;
        scz[t] = -2.0f * cz;
        sC[t]  = cx*cx + cy*cy + cz*cz;    // d^2 = s + C  (read from smem in slow path only)
        sT[t]  = 3.0e38f;
        cnt[t] = 0;
    }
    __syncthreads();

    // ---------- Phase 1: exact top-10 over SAMPLE points -> threshold ----------
    {
        const int rl  = t & 7;             // ray
        const int sub = t >> 3;            // 0..31
        const float cxp = scx[rl], cyp = scy[rl], czp = scz[rl];
        float best[KSEL];
#pragma unroll
        for (int j = 0; j < KSEL; j++) best[j] = 3.0e38f;
        float tloc = 3.0e38f;

#pragma unroll 4
        for (int c = 0; c < SAMPLE / 32; c++) {
            float4 p = g_packed[sub + c * 32];
            float s = fmaf(cxp, p.x, fmaf(cyp, p.y, fmaf(czp, p.z, p.w)));
            if (s < fminf(sTv[rl], tloc)) {
                float v = s;
#pragma unroll
                for (int j = 0; j < KSEL; j++) {
                    if (v < best[j]) { float tv = best[j]; best[j] = v; v = tv; }
                }
                tloc = best[KSEL-1];
                if (tloc < sTv[rl]) sTv[rl] = tloc;   // benign race: any value is a valid bound
            }
        }
        float* smrg = cd2;                 // values-only merge lists
#pragma unroll
        for (int j = 0; j < KSEL; j++) smrg[(rl*32 + sub)*KSEL + j] = best[j];
        __syncthreads();

        for (int stride = 16; stride >= 1; stride >>= 1) {
            if (sub < stride) {
                int a = (rl*32 + sub)*KSEL, b = (rl*32 + sub + stride)*KSEL;
                float ov[KSEL]; int ia = 0, ib = 0;
#pragma unroll
                for (int k = 0; k < KSEL; k++) {
                    float va = smrg[a + ia], vb = smrg[b + ib];
                    if (va <= vb) { ov[k] = va; ia++; } else { ov[k] = vb; ib++; }
                }
#pragma unroll
                for (int k = 0; k < KSEL; k++) smrg[a + k] = ov[k];
            }
            __syncthreads();
        }
        if (t < RPB) { sT[t] = cd2[(t*32)*KSEL + KSEL-1]; cnt[t] = 0; }
        __syncthreads();
    }

    // ---------- Phase 2: lane-owned filter scan (1 LDG.128 per point) ----------
    {
        const float c0x = scx[0], c0y = scy[0], c0z = scz[0], T0 = sT[0];
        const float c1x = scx[1], c1y = scy[1], c1z = scz[1], T1 = sT[1];
        const float c2x = scx[2], c2y = scy[2], c2z = scz[2], T2 = sT[2];
        const float c3x = scx[3], c3y = scy[3], c3z = scz[3], T3 = sT[3];
        const float c4x = scx[4], c4y = scy[4], c4z = scz[4], T4 = sT[4];
        const float c5x = scx[5], c5y = scy[5], c5z = scz[5], T5 = sT[5];
        const float c6x = scx[6], c6y = scy[6], c6z = scz[6], T6 = sT[6];
        const float c7x = scx[7], c7y = scy[7], c7z = scz[7], T7 = sT[7];

        // C is fetched from shared inside the (rare) slow path — keeps it out of regs.
#define PUSH(SV, TR, KK, R) \
        if ((SV) <= (TR)) { int _p = atomicAdd(&cnt[R], 1); \
            if (_p < CAP) { cd2[(R)*CAP + _p] = (SV) + sC[R]; cidx[(R)*CAP + _p] = (KK); } }

        const int stripe = w * 32 + lane;
        const float4* pA = g_packed + stripe;
        const float4* pB = g_packed + stripe + HALF;
#pragma unroll 1
        for (int it = 0; it < MITERS; it++) {
            float4 a = *pA;
            float4 b = *pB;

            float sA0 = fmaf(c0x,a.x,fmaf(c0y,a.y,fmaf(c0z,a.z,a.w)));
            float sA1 = fmaf(c1x,a.x,fmaf(c1y,a.y,fmaf(c1z,a.z,a.w)));
            float sA2 = fmaf(c2x,a.x,fmaf(c2y,a.y,fmaf(c2z,a.z,a.w)));
            float sA3 = fmaf(c3x,a.x,fmaf(c3y,a.y,fmaf(c3z,a.z,a.w)));
            float sA4 = fmaf(c4x,a.x,fmaf(c4y,a.y,fmaf(c4z,a.z,a.w)));
            float sA5 = fmaf(c5x,a.x,fmaf(c5y,a.y,fmaf(c5z,a.z,a.w)));
            float sA6 = fmaf(c6x,a.x,fmaf(c6y,a.y,fmaf(c6z,a.z,a.w)));
            float sA7 = fmaf(c7x,a.x,fmaf(c7y,a.y,fmaf(c7z,a.z,a.w)));
            float sB0 = fmaf(c0x,b.x,fmaf(c0y,b.y,fmaf(c0z,b.z,b.w)));
            float sB1 = fmaf(c1x,b.x,fmaf(c1y,b.y,fmaf(c1z,b.z,b.w)));
            float sB2 = fmaf(c2x,b.x,fmaf(c2y,b.y,fmaf(c2z,b.z,b.w)));
            float sB3 = fmaf(c3x,b.x,fmaf(c3y,b.y,fmaf(c3z,b.z,b.w)));
            float sB4 = fmaf(c4x,b.x,fmaf(c4y,b.y,fmaf(c4z,b.z,b.w)));
            float sB5 = fmaf(c5x,b.x,fmaf(c5y,b.y,fmaf(c5z,b.z,b.w)));
            float sB6 = fmaf(c6x,b.x,fmaf(c6y,b.y,fmaf(c6z,b.z,b.w)));
            float sB7 = fmaf(c7x,b.x,fmaf(c7y,b.y,fmaf(c7z,b.z,b.w)));

            int hA = (sA0<=T0) | (sA1<=T1) | (sA2<=T2) | (sA3<=T3)
                   | (sA4<=T4) | (sA5<=T5) | (sA6<=T6) | (sA7<=T7);
            int hB = (sB0<=T0) | (sB1<=T1) | (sB2<=T2) | (sB3<=T3)
                   | (sB4<=T4) | (sB5<=T5) | (sB6<=T6) | (sB7<=T7);
            if (hA | hB) {
                int kA = stripe + it * 256;
                int kB = kA + HALF;
                if (hA) {
                    PUSH(sA0,T0,kA,0) PUSH(sA1,T1,kA,1)
                    PUSH(sA2,T2,kA,2) PUSH(sA3,T3,kA,3)
                    PUSH(sA4,T4,kA,4) PUSH(sA5,T5,kA,5)
                    PUSH(sA6,T6,kA,6) PUSH(sA7,T7,kA,7)
                }
                if (hB) {
                    PUSH(sB0,T0,kB,0) PUSH(sB1,T1,kB,1)
                    PUSH(sB2,T2,kB,2) PUSH(sB3,T3,kB,3)
                    PUSH(sB4,T4,kB,4) PUSH(sB5,T5,kB,5)
                    PUSH(sB6,T6,kB,6) PUSH(sB7,T7,kB,7)
                }
            }
            pA += 256;
            pB += 256;
        }
        // Tail: 160 points, one per thread
        if (t < NPTS - TAILBASE) {
            int k = TAILBASE + t;
            float4 p = g_packed[k];
            float s0 = fmaf(c0x,p.x,fmaf(c0y,p.y,fmaf(c0z,p.z,p.w)));
            float s1 = fmaf(c1x,p.x,fmaf(c1y,p.y,fmaf(c1z,p.z,p.w)));
            float s2 = fmaf(c2x,p.x,fmaf(c2y,p.y,fmaf(c2z,p.z,p.w)));
            float s3 = fmaf(c3x,p.x,fmaf(c3y,p.y,fmaf(c3z,p.z,p.w)));
            float s4 = fmaf(c4x,p.x,fmaf(c4y,p.y,fmaf(c4z,p.z,p.w)));
            float s5 = fmaf(c5x,p.x,fmaf(c5y,p.y,fmaf(c5z,p.z,p.w)));
            float s6 = fmaf(c6x,p.x,fmaf(c6y,p.y,fmaf(c6z,p.z,p.w)));
            float s7 = fmaf(c7x,p.x,fmaf(c7y,p.y,fmaf(c7z,p.z,p.w)));
            PUSH(s0,T0,k,0) PUSH(s1,T1,k,1) PUSH(s2,T2,k,2) PUSH(s3,T3,k,3)
            PUSH(s4,T4,k,4) PUSH(s5,T5,k,5) PUSH(s6,T6,k,6) PUSH(s7,T7,k,7)
        }
#undef PUSH
    }
    __syncthreads();

    // ---------- Phase 3: warp w selects exact top-10 of ray w ----------
    {
        int n = cnt[w]; if (n > CAP) n = CAP;
        float best[KSEL]; int bxi[KSEL];
#pragma unroll
        for (int j = 0; j < KSEL; j++) { best[j] = 3.0e38f; bxi[j] = 0; }
        for (int j2 = lane; j2 < n; j2 += 32) {
            float v = cd2[w*CAP + j2]; int ii = cidx[w*CAP + j2];
            if (v < best[KSEL-1]) {
#pragma unroll
                for (int j = 0; j < KSEL; j++) {
                    if (v < best[j]) {
                        float tv = best[j]; int ti = bxi[j];
                        best[j] = v; bxi[j] = ii; v = tv; ii = ti;
                    }
                }
            }
        }
        __syncwarp();                       // all candidate reads done before overwrite
#pragma unroll
        for (int j = 0; j < KSEL; j++) {
            cd2 [w*CAP + lane*KSEL + j] = best[j];
            cidx[w*CAP + lane*KSEL + j] = bxi[j];
        }
        __syncwarp();
        for (int stride = 16; stride >= 1; stride >>= 1) {
            if (lane < stride) {
                int a = w*CAP + lane*KSEL, b = w*CAP + (lane + stride)*KSEL;
                float ov[KSEL]; int oi[KSEL];
                int ia = 0, ib = 0;
#pragma unroll
                for (int k = 0; k < KSEL; k++) {
                    float va = cd2[a + ia], vb = cd2[b + ib];
                    if (va <= vb) { ov[k] = va; oi[k] = cidx[a + ia]; ia++; }
                    else          { ov[k] = vb; oi[k] = cidx[b + ib]; ib++; }
                }
#pragma unroll
                for (int k = 0; k < KSEL; k++) { cd2[a + k] = ov[k]; cidx[a + k] = oi[k]; }
            }
            __syncwarp();
        }
        if (lane == 0) {
            float wsum = 0.f, r0 = 0.f, g0 = 0.f, b0 = 0.f;
#pragma unroll
            for (int k = 0; k < KSEL; k++) {
                float d2 = cd2[w*CAP + k];
                int   ii = cidx[w*CAP + k];
                float d  = sqrtf(fmaxf(d2, 0.0f));
                float op = 1.0f / (1.0f + expf(-opac[ii]));
                float ww = expf(-0.1f * d) * op;
                wsum += ww;
                float a0 = 1.0f / (1.0f + expf(-fdc[ii*3+0]));
                float a1 = 1.0f / (1.0f + expf(-fdc[ii*3+1]));
                float a2 = 1.0f / (1.0f + expf(-fdc[ii*3+2]));
                r0 = fmaf(ww, a0, r0);
                g0 = fmaf(ww, a1, g0);
                b0 = fmaf(ww, a2, b0);
            }
            float inv = 1.0f / (wsum + 1e-8f);
            int ray = rayBase + w;
            out[ray*3+0] = r0 * inv;
            out[ray*3+1] = g0 * inv;
            out[ray*3+2] = b0 * inv;
        }
    }
}

extern "C" void kernel_launch(void* const* d_in, const int* in_sizes, int n_in,
                              void* d_out, int out_size)
{
    const float* rays_o = (const float*)d_in[0];
    const float* rays_d = (const float*)d_in[1];
    const float* xyz    = (const float*)d_in[2];
    const float* fdc    = (const float*)d_in[3];
    const float* opac   = (const float*)d_in[4];
    float* out = (float*)d_out;

    pack_kernel<<<(NPTS + 255) / 256, 256>>>(xyz);
    gs_kernel<<<GRID, TPB>>>(rays_o, rays_d, fdc, opac, out);
}